// round 8
// baseline (speedup 1.0000x reference)
#include <cuda_runtime.h>

#define BATCH   8
#define TLEN    8192
#define DIM     512
#define HEADS   8
#define HD      64
#define KSLOTS  64
#define NCH     16
#define CHUNK   512
#define SCALE   0.125f

__device__ float g_Q[KSLOTS * DIM];
__device__ float g_KV[(size_t)BATCH * TLEN * (2 * DIM)];
__device__ float g_Npart[(size_t)NCH * BATCH * KSLOTS * DIM];
__device__ float g_Cpart[(size_t)NCH * BATCH * HEADS * KSLOTS];

__device__ __forceinline__ unsigned long long pack_dup(float x) {
    unsigned long long r; unsigned u = __float_as_uint(x);
    asm("mov.b64 %0, {%1, %1};" : "=l"(r) : "r"(u));
    return r;
}
__device__ __forceinline__ void fma2(unsigned long long& d,
                                     unsigned long long a, unsigned long long b) {
    asm("fma.rn.f32x2 %0, %1, %2, %0;" : "+l"(d) : "l"(a), "l"(b));
}
__device__ __forceinline__ float2 unpack2(unsigned long long v) {
    unsigned lo, hi;
    asm("mov.b64 {%0, %1}, %2;" : "=r"(lo), "=r"(hi) : "l"(v));
    return make_float2(__uint_as_float(lo), __uint_as_float(hi));
}

/* ---------------- kernel 1: slots layernorm -> Q (x 1/sqrt(hd)) ---------------- */
__global__ void slot_q_kernel(const float* __restrict__ sw,
                              const float* __restrict__ gs,
                              const float* __restrict__ bs) {
    __shared__ float red[128];
    int k = blockIdx.x, tid = threadIdx.x;
    float4 x = *(const float4*)&sw[k * DIM + tid * 4];
    red[tid] = x.x + x.y + x.z + x.w;
    __syncthreads();
    for (int o = 64; o > 0; o >>= 1) { if (tid < o) red[tid] += red[tid + o]; __syncthreads(); }
    float mu = red[0] * (1.0f / DIM);
    __syncthreads();
    float dx = x.x - mu, dy = x.y - mu, dz = x.z - mu, dw = x.w - mu;
    red[tid] = dx * dx + dy * dy + dz * dz + dw * dw;
    __syncthreads();
    for (int o = 64; o > 0; o >>= 1) { if (tid < o) red[tid] += red[tid + o]; __syncthreads(); }
    float rstd = rsqrtf(red[0] * (1.0f / DIM) + 1e-5f);
    int d = tid * 4;
    float4 g4 = *(const float4*)&gs[d];
    float4 b4 = *(const float4*)&bs[d];
    float4 q;
    q.x = (dx * rstd * g4.x + b4.x) * SCALE;
    q.y = (dy * rstd * g4.y + b4.y) * SCALE;
    q.z = (dz * rstd * g4.z + b4.z) * SCALE;
    q.w = (dw * rstd * g4.w + b4.w) * SCALE;
    *(float4*)&g_Q[k * DIM + d] = q;
}

/* ---------------- kernel 2: g_KV = [X@Wk^T+bk | X@Wv^T+bv] ----------------
   M=65536, N=1024, K=512. BM=BN=128, BK=16, 256 thr, 8x8/thr, f32x2 acc. */
__global__ void __launch_bounds__(256)
gemm_kv_kernel(const float* __restrict__ X,
               const float* __restrict__ Wk, const float* __restrict__ bk,
               const float* __restrict__ Wv, const float* __restrict__ bv) {
    __shared__ __align__(16) float As[16 * 128];
    __shared__ __align__(16) float Bs[16 * 128];
    int tid = threadIdx.x;
    int n0 = blockIdx.x * 128;
    int m0 = blockIdx.y * 128;
    const float* Wbase = (n0 < DIM) ? (Wk + (size_t)n0 * DIM) : (Wv + (size_t)(n0 - DIM) * DIM);
    const float* bias  = (n0 < DIM) ? (bk + n0) : (bv + (n0 - DIM));
    int tx = tid & 15, ty = tid >> 4;

    unsigned long long acc[8][4];
    #pragma unroll
    for (int i = 0; i < 8; i++)
        #pragma unroll
        for (int j = 0; j < 4; j++) acc[i][j] = 0ULL;

    for (int k0 = 0; k0 < DIM; k0 += 16) {
        float4 aReg[2], bReg[2];
        #pragma unroll
        for (int r = 0; r < 2; r++) {
            int idx = r * 256 + tid;
            int row = idx >> 2, c4 = idx & 3;
            aReg[r] = *(const float4*)&X[(size_t)(m0 + row) * DIM + k0 + c4 * 4];
            bReg[r] = *(const float4*)&Wbase[(size_t)row * DIM + k0 + c4 * 4];
        }
        __syncthreads();
        #pragma unroll
        for (int r = 0; r < 2; r++) {
            int idx = r * 256 + tid;
            int row = idx >> 2, c4 = idx & 3;
            As[(c4 * 4 + 0) * 128 + row] = aReg[r].x;
            As[(c4 * 4 + 1) * 128 + row] = aReg[r].y;
            As[(c4 * 4 + 2) * 128 + row] = aReg[r].z;
            As[(c4 * 4 + 3) * 128 + row] = aReg[r].w;
            Bs[(c4 * 4 + 0) * 128 + row] = bReg[r].x;
            Bs[(c4 * 4 + 1) * 128 + row] = bReg[r].y;
            Bs[(c4 * 4 + 2) * 128 + row] = bReg[r].z;
            Bs[(c4 * 4 + 3) * 128 + row] = bReg[r].w;
        }
        __syncthreads();
        #pragma unroll
        for (int kk = 0; kk < 16; kk++) {
            float4 a0 = *(const float4*)&As[kk * 128 + ty * 8];
            float4 a1 = *(const float4*)&As[kk * 128 + ty * 8 + 4];
            ulonglong2 bq0 = *(const ulonglong2*)&Bs[kk * 128 + tx * 8];
            ulonglong2 bq1 = *(const ulonglong2*)&Bs[kk * 128 + tx * 8 + 4];
            unsigned long long b2[4] = { bq0.x, bq0.y, bq1.x, bq1.y };
            unsigned long long a2[8] = {
                pack_dup(a0.x), pack_dup(a0.y), pack_dup(a0.z), pack_dup(a0.w),
                pack_dup(a1.x), pack_dup(a1.y), pack_dup(a1.z), pack_dup(a1.w)
            };
            #pragma unroll
            for (int i = 0; i < 8; i++)
                #pragma unroll
                for (int j = 0; j < 4; j++)
                    fma2(acc[i][j], a2[i], b2[j]);
        }
    }

    float bvv[8];
    #pragma unroll
    for (int j = 0; j < 8; j++) bvv[j] = bias[tx * 8 + j];
    #pragma unroll
    for (int i = 0; i < 8; i++) {
        float o[8];
        #pragma unroll
        for (int j = 0; j < 4; j++) {
            float2 p = unpack2(acc[i][j]);
            o[2 * j] = p.x + bvv[2 * j];
            o[2 * j + 1] = p.y + bvv[2 * j + 1];
        }
        float* dst = &g_KV[(size_t)(m0 + ty * 8 + i) * (2 * DIM) + n0 + tx * 8];
        *(float4*)dst = make_float4(o[0], o[1], o[2], o[3]);
        *(float4*)(dst + 4) = make_float4(o[4], o[5], o[6], o[7]);
    }
}

/* ---------------- kernel 3: streaming attention, per (chunk, head, batch) ------- */
__global__ void __launch_bounds__(128)
attn_kernel() {
    __shared__ __align__(16) float Qs[64 * 68];
    __shared__ __align__(16) float Kxs[16 * 68];
    __shared__ __align__(16) float Vs[16 * 68];
    __shared__ __align__(16) float ws[16 * 66];
    __shared__ float ms[128], ss[128], redm[16], reds[16];

    int tid = threadIdx.x;
    int c = blockIdx.x, h = blockIdx.y, b = blockIdx.z;

    #pragma unroll
    for (int r = 0; r < 8; r++) {
        int idx = r * 128 + tid;
        int k = idx >> 4, j4 = idx & 15;
        *(float4*)&Qs[k * 68 + j4 * 4] = *(const float4*)&g_Q[k * DIM + h * HD + j4 * 4];
    }

    int tt = tid & 15;
    int k8 = tid >> 4;
    int j0 = tt * 4;
    int kk0 = k8 * 8;

    unsigned long long acc2[8][2];
    float cacc[8];
    #pragma unroll
    for (int i = 0; i < 8; i++) { acc2[i][0] = 0ULL; acc2[i][1] = 0ULL; cacc[i] = 0.f; }

    const size_t kvbase = (size_t)b * TLEN * (2 * DIM) + h * HD;

    for (int it = 0; it < CHUNK / 16; it++) {
        int tbase = c * CHUNK + it * 16;
        __syncthreads();
        /* load 16 tokens of Kx and V */
        #pragma unroll
        for (int r = 0; r < 4; r++) {
            int idx = r * 128 + tid;
            int ti = idx >> 5, qq = idx & 31;
            size_t src = kvbase + (size_t)(tbase + ti) * (2 * DIM) + (qq & 15) * 4
                       + ((qq < 16) ? 0 : DIM);
            float4 v = *(const float4*)&g_KV[src];
            if (qq < 16) *(float4*)&Kxs[ti * 68 + (qq & 15) * 4] = v;
            else         *(float4*)&Vs[ti * 68 + (qq & 15) * 4] = v;
        }
        __syncthreads();

        /* logits: token tt, slots kk0..kk0+7 */
        unsigned long long l2[8];
        #pragma unroll
        for (int i = 0; i < 8; i++) l2[i] = 0ULL;
        #pragma unroll
        for (int jj = 0; jj < HD; jj += 4) {
            ulonglong2 kx2 = *(const ulonglong2*)&Kxs[tt * 68 + jj];
            #pragma unroll
            for (int i = 0; i < 8; i++) {
                ulonglong2 q2 = *(const ulonglong2*)&Qs[(kk0 + i) * 68 + jj];
                fma2(l2[i], q2.x, kx2.x);
                fma2(l2[i], q2.y, kx2.y);
            }
        }
        float l[8];
        #pragma unroll
        for (int i = 0; i < 8; i++) { float2 p = unpack2(l2[i]); l[i] = p.x + p.y; }

        /* softmax over the 64 slots of token tt */
        float lm = l[0];
        #pragma unroll
        for (int i = 1; i < 8; i++) lm = fmaxf(lm, l[i]);
        ms[tid] = lm;
        __syncthreads();
        if (tid < 16) {
            float m = ms[tid];
            #pragma unroll
            for (int g = 1; g < 8; g++) m = fmaxf(m, ms[g * 16 + tid]);
            redm[tid] = m;
        }
        __syncthreads();
        float M = redm[tt];
        float w[8], s = 0.f;
        #pragma unroll
        for (int i = 0; i < 8; i++) { w[i] = __expf(l[i] - M); s += w[i]; }
        ss[tid] = s;
        __syncthreads();
        if (tid < 16) {
            float sm = 0.f;
            #pragma unroll
            for (int g = 0; g < 8; g++) sm += ss[g * 16 + tid];
            reds[tid] = 1.0f / sm;
        }
        __syncthreads();
        float inv = reds[tt];
        #pragma unroll
        for (int i = 0; i < 8; i++) {
            w[i] *= inv;
            cacc[i] += w[i];
            ws[tt * 66 + kk0 + i] = w[i];
        }
        __syncthreads();

        /* N[k][j] += w[t][k] * V[t][j] : 8 slots x 4 dims per thread */
        #pragma unroll
        for (int t = 0; t < 16; t++) {
            const float2* wp = (const float2*)&ws[t * 66 + kk0];
            float2 wa = wp[0], wb = wp[1], wc = wp[2], wdd = wp[3];
            ulonglong2 v2 = *(const ulonglong2*)&Vs[t * 68 + j0];
            float wv[8] = { wa.x, wa.y, wb.x, wb.y, wc.x, wc.y, wdd.x, wdd.y };
            #pragma unroll
            for (int i = 0; i < 8; i++) {
                unsigned long long wd2 = pack_dup(wv[i]);
                fma2(acc2[i][0], wd2, v2.x);
                fma2(acc2[i][1], wd2, v2.y);
            }
        }
    }

    /* flush N partials (exclusive per block) */
    size_t nb = (((size_t)c * BATCH + b) * KSLOTS + kk0) * DIM + h * HD + j0;
    #pragma unroll
    for (int i = 0; i < 8; i++) {
        float2 p0 = unpack2(acc2[i][0]);
        float2 p1 = unpack2(acc2[i][1]);
        *(float4*)&g_Npart[nb + (size_t)i * DIM] = make_float4(p0.x, p0.y, p1.x, p1.y);
    }

    /* flush C partials: reduce over the 16 token-threads */
    __syncthreads();
    #pragma unroll
    for (int i = 0; i < 8; i++) ws[(kk0 + i) * 16 + tt] = cacc[i];
    __syncthreads();
    if (tid < 64) {
        float s = 0.f;
        #pragma unroll
        for (int t = 0; t < 16; t++) s += ws[tid * 16 + t];
        g_Cpart[(((size_t)c * BATCH + b) * HEADS + h) * KSLOTS + tid] = s;
    }
}

/* ---------------- kernel 4: reduce partials, renorm, final layernorm ------------ */
__global__ void __launch_bounds__(128)
final_kernel(const float* __restrict__ ga, const float* __restrict__ bb,
             float* __restrict__ out) {
    __shared__ float red[128];
    __shared__ float csum[8];
    int bk = blockIdx.x;
    int b = bk >> 6, k = bk & 63;
    int tid = threadIdx.x;

    if (tid < 8) {
        float s = 0.f;
        #pragma unroll
        for (int c = 0; c < NCH; c++)
            s += g_Cpart[(((size_t)c * BATCH + b) * HEADS + tid) * KSLOTS + k];
        csum[tid] = s;
    }

    float4 n = make_float4(0.f, 0.f, 0.f, 0.f);
    #pragma unroll
    for (int c = 0; c < NCH; c++) {
        float4 p = *(const float4*)&g_Npart[(((size_t)c * BATCH + b) * KSLOTS + k) * DIM + tid * 4];
        n.x += p.x; n.y += p.y; n.z += p.z; n.w += p.w;
    }
    __syncthreads();
    float inv = 1.0f / (csum[tid >> 4] + 1e-20f);
    float s0 = n.x * inv, s1 = n.y * inv, s2 = n.z * inv, s3 = n.w * inv;

    red[tid] = s0 + s1 + s2 + s3;
    __syncthreads();
    for (int o = 64; o > 0; o >>= 1) { if (tid < o) red[tid] += red[tid + o]; __syncthreads(); }
    float mu = red[0] * (1.0f / DIM);
    __syncthreads();
    float d0 = s0 - mu, d1 = s1 - mu, d2 = s2 - mu, d3 = s3 - mu;
    red[tid] = d0 * d0 + d1 * d1 + d2 * d2 + d3 * d3;
    __syncthreads();
    for (int o = 64; o > 0; o >>= 1) { if (tid < o) red[tid] += red[tid + o]; __syncthreads(); }
    float rstd = rsqrtf(red[0] * (1.0f / DIM) + 1e-5f);

    int d = tid * 4;
    float4 g4 = *(const float4*)&ga[d];
    float4 b4 = *(const float4*)&bb[d];
    float4 o4;
    o4.x = d0 * rstd * g4.x + b4.x;
    o4.y = d1 * rstd * g4.y + b4.y;
    o4.z = d2 * rstd * g4.z + b4.z;
    o4.w = d3 * rstd * g4.w + b4.w;
    *(float4*)&out[((size_t)b * KSLOTS + k) * DIM + d] = o4;
}

extern "C" void kernel_launch(void* const* d_in, const int* in_sizes, int n_in,
                              void* d_out, int out_size) {
    const float* X       = (const float*)d_in[0];
    const float* slots_w = (const float*)d_in[1];
    const float* g_slots = (const float*)d_in[2];
    const float* b_slots = (const float*)d_in[3];
    const float* Wk      = (const float*)d_in[4];
    const float* bk      = (const float*)d_in[5];
    const float* Wv      = (const float*)d_in[6];
    const float* bv      = (const float*)d_in[7];
    const float* g_after = (const float*)d_in[8];
    const float* b_after = (const float*)d_in[9];
    float* out = (float*)d_out;

    slot_q_kernel<<<KSLOTS, 128>>>(slots_w, g_slots, b_slots);
    gemm_kv_kernel<<<dim3(8, (BATCH * TLEN) / 128), 256>>>(X, Wk, bk, Wv, bv);
    attn_kernel<<<dim3(NCH, HEADS, BATCH), 128>>>();
    final_kernel<<<BATCH * KSLOTS, 128>>>(g_after, b_after, out);
}

// round 12
// speedup vs baseline: 2.2667x; 2.2667x over previous
#include <cuda_runtime.h>
#include <cuda_bf16.h>
#include <cstdint>

#define BATCH   8
#define TLEN    8192
#define DIM     512
#define HEADS   8
#define HD      64
#define KSLOTS  64
#define NCH     16
#define CHUNK   512
#define SCALE   0.125f

#define MTOT    (BATCH * TLEN)     /* 65536 */
#define NTOT    (2 * DIM)          /* 1024  */

__device__ float g_Q[KSLOTS * DIM];
__device__ float g_KV[(size_t)MTOT * NTOT];
__device__ float g_Npart[(size_t)NCH * BATCH * KSLOTS * DIM];
__device__ float g_Cpart[(size_t)NCH * BATCH * HEADS * KSLOTS];
__device__ __nv_bfloat16 g_Xh[(size_t)MTOT * DIM];
__device__ __nv_bfloat16 g_Xl[(size_t)MTOT * DIM];
__device__ __nv_bfloat16 g_Wh[(size_t)NTOT * DIM];
__device__ __nv_bfloat16 g_Wl[(size_t)NTOT * DIM];

/* ---------------- packed f32x2 helpers ---------------- */
__device__ __forceinline__ unsigned long long pack_dup(float x) {
    unsigned long long r; unsigned u = __float_as_uint(x);
    asm("mov.b64 %0, {%1, %1};" : "=l"(r) : "r"(u));
    return r;
}
__device__ __forceinline__ void fma2(unsigned long long& d,
                                     unsigned long long a, unsigned long long b) {
    asm("fma.rn.f32x2 %0, %1, %2, %0;" : "+l"(d) : "l"(a), "l"(b));
}
__device__ __forceinline__ float2 unpack2(unsigned long long v) {
    unsigned lo, hi;
    asm("mov.b64 {%0, %1}, %2;" : "=r"(lo), "=r"(hi) : "l"(v));
    return make_float2(__uint_as_float(lo), __uint_as_float(hi));
}

/* ---------------- mma / ldmatrix / cp.async helpers (base PTX, no 'a' features) -- */
__device__ __forceinline__ uint32_t smem_u32(const void* p) {
    uint32_t a;
    asm("{ .reg .u64 t; cvta.to.shared.u64 t, %1; cvt.u32.u64 %0, t; }" : "=r"(a) : "l"(p));
    return a;
}
__device__ __forceinline__ void ldsm4(uint32_t* r, uint32_t addr) {
    asm volatile("ldmatrix.sync.aligned.m8n8.x4.shared.b16 {%0,%1,%2,%3}, [%4];"
        : "=r"(r[0]), "=r"(r[1]), "=r"(r[2]), "=r"(r[3]) : "r"(addr));
}
__device__ __forceinline__ void mma_bf16(float* c, const uint32_t* a, const uint32_t* b) {
    asm volatile("mma.sync.aligned.m16n8k16.row.col.f32.bf16.bf16.f32 "
        "{%0,%1,%2,%3}, {%4,%5,%6,%7}, {%8,%9}, {%0,%1,%2,%3};"
        : "+f"(c[0]), "+f"(c[1]), "+f"(c[2]), "+f"(c[3])
        : "r"(a[0]), "r"(a[1]), "r"(a[2]), "r"(a[3]), "r"(b[0]), "r"(b[1]));
}
__device__ __forceinline__ void cp16(uint32_t dst, const void* src) {
    asm volatile("cp.async.cg.shared.global [%0], [%1], 16;"
        :: "r"(dst), "l"(__cvta_generic_to_global(src)) : "memory");
}
#define CP_COMMIT asm volatile("cp.async.commit_group;" ::: "memory")
#define CP_WAIT1  asm volatile("cp.async.wait_group 1;" ::: "memory")
#define CP_WAIT0  asm volatile("cp.async.wait_group 0;" ::: "memory")

#define SWZ(x) ((x) ^ ((((x) >> 3)) & 0x70))

/* GEMM smem: 2 stages x (Ah,Al,Bh,Bl each 128x64 bf16 = 16KB) = 128KB dynamic */
#define STG      65536
#define OFF_AH   0
#define OFF_AL   16384
#define OFF_BH   32768
#define OFF_BL   49152
#define GEMM_SMEM (2 * STG)

/* ---------------- kernel 0a: X -> bf16 hi/lo ---------------- */
__global__ void __launch_bounds__(256)
convert_x_kernel(const float* __restrict__ X) {
    size_t i = ((size_t)blockIdx.x * 256 + threadIdx.x) * 8;
    float4 a = *(const float4*)&X[i];
    float4 b = *(const float4*)&X[i + 4];
    float v[8] = { a.x, a.y, a.z, a.w, b.x, b.y, b.z, b.w };
    uint32_t hp[4], lp[4];
    #pragma unroll
    for (int q = 0; q < 4; q++) {
        __nv_bfloat16 h0 = __float2bfloat16(v[2 * q]);
        __nv_bfloat16 h1 = __float2bfloat16(v[2 * q + 1]);
        __nv_bfloat16 l0 = __float2bfloat16(v[2 * q] - __bfloat162float(h0));
        __nv_bfloat16 l1 = __float2bfloat16(v[2 * q + 1] - __bfloat162float(h1));
        hp[q] = (uint32_t)__bfloat16_as_ushort(h0) | ((uint32_t)__bfloat16_as_ushort(h1) << 16);
        lp[q] = (uint32_t)__bfloat16_as_ushort(l0) | ((uint32_t)__bfloat16_as_ushort(l1) << 16);
    }
    *(uint4*)&g_Xh[i] = make_uint4(hp[0], hp[1], hp[2], hp[3]);
    *(uint4*)&g_Xl[i] = make_uint4(lp[0], lp[1], lp[2], lp[3]);
}

/* ---------------- kernel 0b: [Wk;Wv] -> bf16 hi/lo ---------------- */
__global__ void __launch_bounds__(256)
convert_w_kernel(const float* __restrict__ Wk, const float* __restrict__ Wv) {
    size_t i = ((size_t)blockIdx.x * 256 + threadIdx.x) * 8;
    size_t n = i >> 9, k = i & 511;
    const float* src = (n < DIM) ? &Wk[n * DIM + k] : &Wv[(n - DIM) * DIM + k];
    float4 a = *(const float4*)src;
    float4 b = *(const float4*)(src + 4);
    float v[8] = { a.x, a.y, a.z, a.w, b.x, b.y, b.z, b.w };
    uint32_t hp[4], lp[4];
    #pragma unroll
    for (int q = 0; q < 4; q++) {
        __nv_bfloat16 h0 = __float2bfloat16(v[2 * q]);
        __nv_bfloat16 h1 = __float2bfloat16(v[2 * q + 1]);
        __nv_bfloat16 l0 = __float2bfloat16(v[2 * q] - __bfloat162float(h0));
        __nv_bfloat16 l1 = __float2bfloat16(v[2 * q + 1] - __bfloat162float(h1));
        hp[q] = (uint32_t)__bfloat16_as_ushort(h0) | ((uint32_t)__bfloat16_as_ushort(h1) << 16);
        lp[q] = (uint32_t)__bfloat16_as_ushort(l0) | ((uint32_t)__bfloat16_as_ushort(l1) << 16);
    }
    *(uint4*)&g_Wh[i] = make_uint4(hp[0], hp[1], hp[2], hp[3]);
    *(uint4*)&g_Wl[i] = make_uint4(lp[0], lp[1], lp[2], lp[3]);
}

/* ---------------- kernel 1: slots layernorm -> Q (x 1/sqrt(hd)) ---------------- */
__global__ void slot_q_kernel(const float* __restrict__ sw,
                              const float* __restrict__ gs,
                              const float* __restrict__ bs) {
    __shared__ float red[128];
    int k = blockIdx.x, tid = threadIdx.x;
    float4 x = *(const float4*)&sw[k * DIM + tid * 4];
    red[tid] = x.x + x.y + x.z + x.w;
    __syncthreads();
    for (int o = 64; o > 0; o >>= 1) { if (tid < o) red[tid] += red[tid + o]; __syncthreads(); }
    float mu = red[0] * (1.0f / DIM);
    __syncthreads();
    float dx = x.x - mu, dy = x.y - mu, dz = x.z - mu, dw = x.w - mu;
    red[tid] = dx * dx + dy * dy + dz * dz + dw * dw;
    __syncthreads();
    for (int o = 64; o > 0; o >>= 1) { if (tid < o) red[tid] += red[tid + o]; __syncthreads(); }
    float rstd = rsqrtf(red[0] * (1.0f / DIM) + 1e-5f);
    int d = tid * 4;
    float4 g4 = *(const float4*)&gs[d];
    float4 b4 = *(const float4*)&bs[d];
    float4 q;
    q.x = (dx * rstd * g4.x + b4.x) * SCALE;
    q.y = (dy * rstd * g4.y + b4.y) * SCALE;
    q.z = (dz * rstd * g4.z + b4.z) * SCALE;
    q.w = (dw * rstd * g4.w + b4.w) * SCALE;
    *(float4*)&g_Q[k * DIM + d] = q;
}

/* ---------------- kernel 2: bf16x3 HMMA GEMM -> g_KV ----------------
   CTA: 128(M) x 128(N), BK=64, 8 warps (2x4), warp tile 64x32.
   D = Ah*Bh + Ah*Bl + Al*Bh, fp32 acc; bias fused in epilogue. */
__global__ void __launch_bounds__(256, 1)
gemm_mma_kernel(const float* __restrict__ bk, const float* __restrict__ bv) {
    extern __shared__ char smem[];
    const int tid = threadIdx.x;
    const int lane = tid & 31, wid = tid >> 5;
    const int n0 = blockIdx.x * 128;
    const int m0 = blockIdx.y * 128;
    const uint32_t sb = smem_u32(smem);

    const int wm = (wid >> 2) * 64;   /* warp m offset in CTA tile */
    const int wn = (wid & 3) * 32;    /* warp n offset */

    float acc[4][4][4];
    #pragma unroll
    for (int i = 0; i < 4; i++)
        #pragma unroll
        for (int j = 0; j < 4; j++)
            #pragma unroll
            for (int q = 0; q < 4; q++) acc[i][j][q] = 0.f;

    /* ldmatrix lane addressing (row within CTA tile, col byte offset) */
    const int arow  = wm + (lane & 15);
    const int acolb = (lane >> 4) * 16;
    const int brow  = wn + ((lane >> 4) & 1) * 8 + (lane & 7);
    const int bcolb = ((lane >> 3) & 1) * 16;

    /* stage loader: 16B granules, 4 iters x 4 matrices per thread */
    auto load_stage = [&](int c, int buf) {
        uint32_t base = sb + buf * STG;
        #pragma unroll
        for (int r = 0; r < 4; r++) {
            int idx = r * 256 + tid;
            int row = idx >> 3, q = idx & 7;
            uint32_t off = SWZ(row * 128 + q * 16);
            size_t srcA = (size_t)(m0 + row) * DIM + c * 64 + q * 8;
            size_t srcB = (size_t)(n0 + row) * DIM + c * 64 + q * 8;
            cp16(base + OFF_AH + off, &g_Xh[srcA]);
            cp16(base + OFF_AL + off, &g_Xl[srcA]);
            cp16(base + OFF_BH + off, &g_Wh[srcB]);
            cp16(base + OFF_BL + off, &g_Wl[srcB]);
        }
    };

    load_stage(0, 0);
    CP_COMMIT;

    for (int c = 0; c < 8; c++) {
        if (c < 7) { load_stage(c + 1, (c + 1) & 1); CP_COMMIT; CP_WAIT1; }
        else       { CP_WAIT0; }
        __syncthreads();

        uint32_t ahB = sb + (c & 1) * STG;
        uint32_t alB = ahB + OFF_AL, bhB = ahB + OFF_BH, blB = ahB + OFF_BL;

        #pragma unroll
        for (int ks = 0; ks < 4; ks++) {
            int kb = ks * 32;  /* 16 cols * 2B */

            uint32_t ah[16];
            #pragma unroll
            for (int mt = 0; mt < 4; mt++)
                ldsm4(&ah[mt * 4], ahB + SWZ((arow + mt * 16) * 128 + kb + acolb));
            uint32_t bh[8];
            #pragma unroll
            for (int p = 0; p < 2; p++)
                ldsm4(&bh[p * 4], bhB + SWZ((brow + p * 16) * 128 + kb + bcolb));

            #pragma unroll
            for (int mt = 0; mt < 4; mt++)
                #pragma unroll
                for (int nt = 0; nt < 4; nt++)
                    mma_bf16(acc[mt][nt], &ah[mt * 4], &bh[nt * 2]);

            uint32_t bl[8];
            #pragma unroll
            for (int p = 0; p < 2; p++)
                ldsm4(&bl[p * 4], blB + SWZ((brow + p * 16) * 128 + kb + bcolb));
            #pragma unroll
            for (int mt = 0; mt < 4; mt++)
                #pragma unroll
                for (int nt = 0; nt < 4; nt++)
                    mma_bf16(acc[mt][nt], &ah[mt * 4], &bl[nt * 2]);

            uint32_t al[16];
            #pragma unroll
            for (int mt = 0; mt < 4; mt++)
                ldsm4(&al[mt * 4], alB + SWZ((arow + mt * 16) * 128 + kb + acolb));
            #pragma unroll
            for (int mt = 0; mt < 4; mt++)
                #pragma unroll
                for (int nt = 0; nt < 4; nt++)
                    mma_bf16(acc[mt][nt], &al[mt * 4], &bh[nt * 2]);
        }
        __syncthreads();
    }

    /* epilogue: D frag (c0,c1)=row g, (c2,c3)=row g+8, cols (lane&3)*2 .. +1 */
    const float* bias = (n0 < DIM) ? (bk + n0) : (bv + (n0 - DIM));
    int g = lane >> 2, qn = (lane & 3) * 2;
    #pragma unroll
    for (int mt = 0; mt < 4; mt++) {
        int row = m0 + wm + mt * 16 + g;
        #pragma unroll
        for (int nt = 0; nt < 4; nt++) {
            int col = wn + nt * 8 + qn;
            float b0 = bias[col], b1 = bias[col + 1];
            float* cc = acc[mt][nt];
            *(float2*)&g_KV[(size_t)row * NTOT + n0 + col] =
                make_float2(cc[0] + b0, cc[1] + b1);
            *(float2*)&g_KV[(size_t)(row + 8) * NTOT + n0 + col] =
                make_float2(cc[2] + b0, cc[3] + b1);
        }
    }
}

/* ---------------- kernel 3: streaming attention, per (chunk, head, batch) ------- */
__global__ void __launch_bounds__(128)
attn_kernel() {
    __shared__ __align__(16) float Qs[64 * 68];
    __shared__ __align__(16) float Kxs[16 * 68];
    __shared__ __align__(16) float Vs[16 * 68];
    __shared__ __align__(16) float ws[16 * 66];
    __shared__ float ms[128], ss[128], redm[16], reds[16];

    int tid = threadIdx.x;
    int c = blockIdx.x, h = blockIdx.y, b = blockIdx.z;

    #pragma unroll
    for (int r = 0; r < 8; r++) {
        int idx = r * 128 + tid;
        int k = idx >> 4, j4 = idx & 15;
        *(float4*)&Qs[k * 68 + j4 * 4] = *(const float4*)&g_Q[k * DIM + h * HD + j4 * 4];
    }

    int tt = tid & 15;
    int k8 = tid >> 4;
    int j0 = tt * 4;
    int kk0 = k8 * 8;

    unsigned long long acc2[8][2];
    float cacc[8];
    #pragma unroll
    for (int i = 0; i < 8; i++) { acc2[i][0] = 0ULL; acc2[i][1] = 0ULL; cacc[i] = 0.f; }

    const size_t kvbase = (size_t)b * TLEN * NTOT + h * HD;

    for (int it = 0; it < CHUNK / 16; it++) {
        int tbase = c * CHUNK + it * 16;
        __syncthreads();
        #pragma unroll
        for (int r = 0; r < 4; r++) {
            int idx = r * 128 + tid;
            int ti = idx >> 5, qq = idx & 31;
            size_t src = kvbase + (size_t)(tbase + ti) * NTOT + (qq & 15) * 4
                       + ((qq < 16) ? 0 : DIM);
            float4 v = *(const float4*)&g_KV[src];
            if (qq < 16) *(float4*)&Kxs[ti * 68 + (qq & 15) * 4] = v;
            else         *(float4*)&Vs[ti * 68 + (qq & 15) * 4] = v;
        }
        __syncthreads();

        unsigned long long l2[8];
        #pragma unroll
        for (int i = 0; i < 8; i++) l2[i] = 0ULL;
        #pragma unroll
        for (int jj = 0; jj < HD; jj += 4) {
            ulonglong2 kx2 = *(const ulonglong2*)&Kxs[tt * 68 + jj];
            #pragma unroll
            for (int i = 0; i < 8; i++) {
                ulonglong2 q2 = *(const ulonglong2*)&Qs[(kk0 + i) * 68 + jj];
                fma2(l2[i], q2.x, kx2.x);
                fma2(l2[i], q2.y, kx2.y);
            }
        }
        float l[8];
        #pragma unroll
        for (int i = 0; i < 8; i++) { float2 p = unpack2(l2[i]); l[i] = p.x + p.y; }

        float lm = l[0];
        #pragma unroll
        for (int i = 1; i < 8; i++) lm = fmaxf(lm, l[i]);
        ms[tid] = lm;
        __syncthreads();
        if (tid < 16) {
            float m = ms[tid];
            #pragma unroll
            for (int g = 1; g < 8; g++) m = fmaxf(m, ms[g * 16 + tid]);
            redm[tid] = m;
        }
        __syncthreads();
        float M = redm[tt];
        float w[8], s = 0.f;
        #pragma unroll
        for (int i = 0; i < 8; i++) { w[i] = __expf(l[i] - M); s += w[i]; }
        ss[tid] = s;
        __syncthreads();
        if (tid < 16) {
            float sm = 0.f;
            #pragma unroll
            for (int g = 0; g < 8; g++) sm += ss[g * 16 + tid];
            reds[tid] = 1.0f / sm;
        }
        __syncthreads();
        float inv = reds[tt];
        #pragma unroll
        for (int i = 0; i < 8; i++) {
            w[i] *= inv;
            cacc[i] += w[i];
            ws[tt * 66 + kk0 + i] = w[i];
        }
        __syncthreads();

        #pragma unroll
        for (int t = 0; t < 16; t++) {
            const float2* wp = (const float2*)&ws[t * 66 + kk0];
            float2 wa = wp[0], wb = wp[1], wc = wp[2], wdd = wp[3];
            ulonglong2 v2 = *(const ulonglong2*)&Vs[t * 68 + j0];
            float wv[8] = { wa.x, wa.y, wb.x, wb.y, wc.x, wc.y, wdd.x, wdd.y };
            #pragma unroll
            for (int i = 0; i < 8; i++) {
                unsigned long long wd2 = pack_dup(wv[i]);
                fma2(acc2[i][0], wd2, v2.x);
                fma2(acc2[i][1], wd2, v2.y);
            }
        }
    }

    size_t nb = (((size_t)c * BATCH + b) * KSLOTS + kk0) * DIM + h * HD + j0;
    #pragma unroll
    for (int i = 0; i < 8; i++) {
        float2 p0 = unpack2(acc2[i][0]);
        float2 p1 = unpack2(acc2[i][1]);
        *(float4*)&g_Npart[nb + (size_t)i * DIM] = make_float4(p0.x, p0.y, p1.x, p1.y);
    }

    __syncthreads();
    #pragma unroll
    for (int i = 0; i < 8; i++) ws[(kk0 + i) * 16 + tt] = cacc[i];
    __syncthreads();
    if (tid < 64) {
        float s = 0.f;
        #pragma unroll
        for (int t = 0; t < 16; t++) s += ws[tid * 16 + t];
        g_Cpart[(((size_t)c * BATCH + b) * HEADS + h) * KSLOTS + tid] = s;
    }
}

/* ---------------- kernel 4: reduce partials, renorm, final layernorm ------------ */
__global__ void __launch_bounds__(128)
final_kernel(const float* __restrict__ ga, const float* __restrict__ bb,
             float* __restrict__ out) {
    __shared__ float red[128];
    __shared__ float csum[8];
    int bkx = blockIdx.x;
    int b = bkx >> 6, k = bkx & 63;
    int tid = threadIdx.x;

    if (tid < 8) {
        float s = 0.f;
        #pragma unroll
        for (int c = 0; c < NCH; c++)
            s += g_Cpart[(((size_t)c * BATCH + b) * HEADS + tid) * KSLOTS + k];
        csum[tid] = s;
    }

    float4 n = make_float4(0.f, 0.f, 0.f, 0.f);
    #pragma unroll
    for (int c = 0; c < NCH; c++) {
        float4 p = *(const float4*)&g_Npart[(((size_t)c * BATCH + b) * KSLOTS + k) * DIM + tid * 4];
        n.x += p.x; n.y += p.y; n.z += p.z; n.w += p.w;
    }
    __syncthreads();
    float inv = 1.0f / (csum[tid >> 4] + 1e-20f);
    float s0 = n.x * inv, s1 = n.y * inv, s2 = n.z * inv, s3 = n.w * inv;

    red[tid] = s0 + s1 + s2 + s3;
    __syncthreads();
    for (int o = 64; o > 0; o >>= 1) { if (tid < o) red[tid] += red[tid + o]; __syncthreads(); }
    float mu = red[0] * (1.0f / DIM);
    __syncthreads();
    float d0 = s0 - mu, d1 = s1 - mu, d2 = s2 - mu, d3 = s3 - mu;
    red[tid] = d0 * d0 + d1 * d1 + d2 * d2 + d3 * d3;
    __syncthreads();
    for (int o = 64; o > 0; o >>= 1) { if (tid < o) red[tid] += red[tid + o]; __syncthreads(); }
    float rstd = rsqrtf(red[0] * (1.0f / DIM) + 1e-5f);

    int d = tid * 4;
    float4 g4 = *(const float4*)&ga[d];
    float4 b4 = *(const float4*)&bb[d];
    float4 o4;
    o4.x = d0 * rstd * g4.x + b4.x;
    o4.y = d1 * rstd * g4.y + b4.y;
    o4.z = d2 * rstd * g4.z + b4.z;
    o4.w = d3 * rstd * g4.w + b4.w;
    *(float4*)&out[((size_t)b * KSLOTS + k) * DIM + d] = o4;
}

extern "C" void kernel_launch(void* const* d_in, const int* in_sizes, int n_in,
                              void* d_out, int out_size) {
    const float* X       = (const float*)d_in[0];
    const float* slots_w = (const float*)d_in[1];
    const float* g_slots = (const float*)d_in[2];
    const float* b_slots = (const float*)d_in[3];
    const float* Wk      = (const float*)d_in[4];
    const float* bk      = (const float*)d_in[5];
    const float* Wv      = (const float*)d_in[6];
    const float* bv      = (const float*)d_in[7];
    const float* g_after = (const float*)d_in[8];
    const float* b_after = (const float*)d_in[9];
    float* out = (float*)d_out;

    cudaFuncSetAttribute(gemm_mma_kernel,
                         cudaFuncAttributeMaxDynamicSharedMemorySize, GEMM_SMEM);

    slot_q_kernel<<<KSLOTS, 128>>>(slots_w, g_slots, b_slots);
    convert_x_kernel<<<(MTOT * DIM) / (256 * 8), 256>>>(X);
    convert_w_kernel<<<(NTOT * DIM) / (256 * 8), 256>>>(Wk, Wv);
    gemm_mma_kernel<<<dim3(NTOT / 128, MTOT / 128), 256, GEMM_SMEM>>>(bk, bv);
    attn_kernel<<<dim3(NCH, HEADS, BATCH), 128>>>();
    final_kernel<<<BATCH * KSLOTS, 128>>>(g_after, b_after, out);
}